// round 6
// baseline (speedup 1.0000x reference)
#include <cuda_runtime.h>
#include <cuda_bf16.h>
#include <math.h>

// Problem dims
#define Bq   128
#define Sq   256
#define Eq   512
#define Hq   1024
#define Vq   2048
#define G4H  4096   // 4*H
#define Kout 2048   // 2*H (output GEMM K)
#define Mout (Bq * Sq)

// ---------------------------------------------------------------------------
// Scratch (device globals; no allocation allowed)
// ---------------------------------------------------------------------------
__device__ float g_Wtf[Eq * G4H];            //  8 MB: Wf gate-interleaved
__device__ float g_Wtb[Eq * G4H];
__device__ float g_btf[G4H];
__device__ float g_btb[G4H];
__device__ float g_Utf[Hq * G4H];            // 16 MB: Uf gate-interleaved
__device__ float g_Utb[Hq * G4H];
__device__ float g_embWtf[Vq * G4H];         // 32 MB
__device__ float g_embWtb[Vq * G4H];
__device__ float g_h[2][2][Bq * Hq];
__device__ float g_c[2][Bq * Hq];
// hcat as split-bf16 (A operand of the output GEMM), row m = b*S+s, col = dir*H+j
__device__ __nv_bfloat16 g_Ahi[Mout * Kout]; // 128 MB
__device__ __nv_bfloat16 g_Alo[Mout * Kout]; // 128 MB
// Wd transposed + split: B[n][k] = Wd[k][n]
__device__ __nv_bfloat16 g_Bhi[Vq * Kout];   // 8 MB
__device__ __nv_bfloat16 g_Blo[Vq * Kout];   // 8 MB

// ---------------------------------------------------------------------------
// f32x2 packed-FMA helpers
// ---------------------------------------------------------------------------
__device__ __forceinline__ unsigned long long dup2(float x) {
    unsigned long long r;
    asm("mov.b64 %0, {%1, %1};" : "=l"(r) : "f"(x));
    return r;
}
__device__ __forceinline__ void ffma2(unsigned long long &acc,
                                      unsigned long long a,
                                      unsigned long long b) {
    asm("fma.rn.f32x2 %0, %1, %2, %0;" : "+l"(acc) : "l"(a), "l"(b));
}
__device__ __forceinline__ float2 unpack2(unsigned long long v) {
    float2 f;
    asm("mov.b64 {%0, %1}, %2;" : "=f"(f.x), "=f"(f.y) : "l"(v));
    return f;
}
__device__ __forceinline__ float sigmoidf_fast(float x) {
    return __fdividef(1.f, 1.f + __expf(-x));
}
__device__ __forceinline__ unsigned smem_to_u32(const void* p) {
    unsigned a;
    asm("{ .reg .u64 t; cvta.to.shared.u64 t, %1; cvt.u32.u64 %0, t; }"
        : "=r"(a) : "l"(p));
    return a;
}

// ---------------------------------------------------------------------------
// sm_80+ portable async-copy + ldmatrix + HMMA (no arch-specific features)
// ---------------------------------------------------------------------------
__device__ __forceinline__ void cp_async16(unsigned smem_addr, const void* gptr) {
    asm volatile("cp.async.cg.shared.global [%0], [%1], 16;"
                 :: "r"(smem_addr), "l"(gptr));
}
#define CP_COMMIT() asm volatile("cp.async.commit_group;" ::: "memory")
#define CP_WAIT(n)  asm volatile("cp.async.wait_group %0;" :: "n"(n) : "memory")

__device__ __forceinline__ void ldmatrix_x4(unsigned* r, unsigned addr) {
    asm volatile("ldmatrix.sync.aligned.m8n8.x4.shared.b16 {%0,%1,%2,%3}, [%4];"
                 : "=r"(r[0]), "=r"(r[1]), "=r"(r[2]), "=r"(r[3]) : "r"(addr));
}
__device__ __forceinline__ void mma_bf16(float* c, const unsigned* a,
                                         const unsigned* b) {
    asm volatile(
        "mma.sync.aligned.m16n8k16.row.col.f32.bf16.bf16.f32 "
        "{%0,%1,%2,%3}, {%4,%5,%6,%7}, {%8,%9}, {%0,%1,%2,%3};"
        : "+f"(c[0]), "+f"(c[1]), "+f"(c[2]), "+f"(c[3])
        : "r"(a[0]), "r"(a[1]), "r"(a[2]), "r"(a[3]), "r"(b[0]), "r"(b[1]));
}

// ---------------------------------------------------------------------------
// Zero the recurrent state
// ---------------------------------------------------------------------------
__global__ void init_state_kernel() {
    int i = blockIdx.x * blockDim.x + threadIdx.x;
    if (i < Bq * Hq) {
        g_h[0][0][i] = 0.f; g_h[0][1][i] = 0.f;
        g_h[1][0][i] = 0.f; g_h[1][1][i] = 0.f;
        g_c[0][i]    = 0.f; g_c[1][i]    = 0.f;
    }
}

// ---------------------------------------------------------------------------
// Gate-interleave W, b:  Wt[e][j*4+g] = W[e][g*H+j]
// ---------------------------------------------------------------------------
__global__ void interleave_W_kernel(const float* __restrict__ Wf,
                                    const float* __restrict__ Wb,
                                    const float* __restrict__ bf,
                                    const float* __restrict__ bb) {
    int idx = blockIdx.x * blockDim.x + threadIdx.x;
    if (idx < Eq * G4H) {
        int e = idx >> 12;
        int c = idx & 4095;
        int src = e * G4H + (c & 3) * Hq + (c >> 2);
        g_Wtf[idx] = Wf[src];
        g_Wtb[idx] = Wb[src];
    }
    if (idx < G4H) {
        int src = (idx & 3) * Hq + (idx >> 2);
        g_btf[idx] = bf[src];
        g_btb[idx] = bb[src];
    }
}

__global__ void interleave_U_kernel(const float* __restrict__ Uf,
                                    const float* __restrict__ Ub) {
    int idx = blockIdx.x * blockDim.x + threadIdx.x;
    if (idx < Hq * G4H) {
        int k = idx >> 12;
        int c = idx & 4095;
        int src = k * G4H + (c & 3) * Hq + (c >> 2);
        g_Utf[idx] = Uf[src];
        g_Utb[idx] = Ub[src];
    }
}

// ---------------------------------------------------------------------------
// Transpose + split Wd:  Bhi/Blo[n][k] = split_bf16(Wd[k][n])
// ---------------------------------------------------------------------------
__global__ void split_transpose_Wd_kernel(const float* __restrict__ Wd) {
    __shared__ float ts[32][33];
    int n0 = blockIdx.x * 32;
    int k0 = blockIdx.y * 32;
    int tx = threadIdx.x, ty = threadIdx.y;
#pragma unroll
    for (int i = 0; i < 32; i += 8)
        ts[ty + i][tx] = Wd[(size_t)(k0 + ty + i) * Vq + n0 + tx];
    __syncthreads();
#pragma unroll
    for (int i = 0; i < 32; i += 8) {
        float v = ts[tx][ty + i];            // Wd[k0+tx][n0+ty+i]
        __nv_bfloat16 hi = __float2bfloat16(v);
        float rem = v - __bfloat162float(hi);
        size_t o = (size_t)(n0 + ty + i) * Kout + k0 + tx;
        g_Bhi[o] = hi;
        g_Blo[o] = __float2bfloat16(rem);
    }
}

// ---------------------------------------------------------------------------
// Generic tiled fp32 GEMM (embW precompute):  C = A @ B + bias
// ---------------------------------------------------------------------------
__global__ __launch_bounds__(256) void gemm_bias_kernel(
    const float* __restrict__ A, const float* __restrict__ B,
    const float* __restrict__ bias, float* __restrict__ C,
    int M, int N, int K)
{
    __shared__ float As[16][128];
    __shared__ float Bs[16][128];

    const int tid = threadIdx.x;
    const int n0  = blockIdx.x * 128;
    const int m0  = blockIdx.y * 128;

    const int a_kq = tid & 3;
    const int a_r  = tid >> 2;
    const int b_c4 = tid & 31;
    const int b_k  = tid >> 5;

    const int trow = tid >> 4;
    const int tcol = tid & 15;

    unsigned long long acc[4][8];
#pragma unroll
    for (int i = 0; i < 4; i++)
#pragma unroll
        for (int j = 0; j < 8; j++) acc[i][j] = 0ull;

    float4 pa0, pa1, pb0, pb1;
    pa0 = *reinterpret_cast<const float4*>(&A[(m0 + a_r)      * K + a_kq * 4]);
    pa1 = *reinterpret_cast<const float4*>(&A[(m0 + a_r + 64) * K + a_kq * 4]);
    pb0 = *reinterpret_cast<const float4*>(&B[(b_k)     * N + n0 + b_c4 * 4]);
    pb1 = *reinterpret_cast<const float4*>(&B[(b_k + 8) * N + n0 + b_c4 * 4]);

    for (int kc = 0; kc < K; kc += 16) {
        As[a_kq * 4 + 0][a_r] = pa0.x;
        As[a_kq * 4 + 1][a_r] = pa0.y;
        As[a_kq * 4 + 2][a_r] = pa0.z;
        As[a_kq * 4 + 3][a_r] = pa0.w;
        As[a_kq * 4 + 0][a_r + 64] = pa1.x;
        As[a_kq * 4 + 1][a_r + 64] = pa1.y;
        As[a_kq * 4 + 2][a_r + 64] = pa1.z;
        As[a_kq * 4 + 3][a_r + 64] = pa1.w;
        *reinterpret_cast<float4*>(&Bs[b_k][b_c4 * 4])     = pb0;
        *reinterpret_cast<float4*>(&Bs[b_k + 8][b_c4 * 4]) = pb1;
        __syncthreads();

        const int kn = kc + 16;
        if (kn < K) {
            pa0 = *reinterpret_cast<const float4*>(&A[(m0 + a_r)      * K + kn + a_kq * 4]);
            pa1 = *reinterpret_cast<const float4*>(&A[(m0 + a_r + 64) * K + kn + a_kq * 4]);
            pb0 = *reinterpret_cast<const float4*>(&B[(kn + b_k)     * N + n0 + b_c4 * 4]);
            pb1 = *reinterpret_cast<const float4*>(&B[(kn + b_k + 8) * N + n0 + b_c4 * 4]);
        }

#pragma unroll
        for (int k = 0; k < 16; k++) {
            const ulonglong2* ap =
                reinterpret_cast<const ulonglong2*>(&As[k][trow * 8]);
            ulonglong2 av0 = ap[0];
            ulonglong2 av1 = ap[1];
            unsigned long long a4[4] = {av0.x, av0.y, av1.x, av1.y};

            float4 bv0 = *reinterpret_cast<const float4*>(&Bs[k][tcol * 8]);
            float4 bv1 = *reinterpret_cast<const float4*>(&Bs[k][tcol * 8 + 4]);
            unsigned long long bd[8];
            bd[0] = dup2(bv0.x); bd[1] = dup2(bv0.y);
            bd[2] = dup2(bv0.z); bd[3] = dup2(bv0.w);
            bd[4] = dup2(bv1.x); bd[5] = dup2(bv1.y);
            bd[6] = dup2(bv1.z); bd[7] = dup2(bv1.w);

#pragma unroll
            for (int ip = 0; ip < 4; ip++)
#pragma unroll
                for (int j = 0; j < 8; j++)
                    ffma2(acc[ip][j], a4[ip], bd[j]);
        }
        __syncthreads();
    }

    float bsv[8];
#pragma unroll
    for (int j = 0; j < 8; j++) bsv[j] = bias[n0 + tcol * 8 + j];

#pragma unroll
    for (int ip = 0; ip < 4; ip++) {
        float2 v[8];
#pragma unroll
        for (int j = 0; j < 8; j++) v[j] = unpack2(acc[ip][j]);
        int r0 = m0 + trow * 8 + ip * 2;
        float* c0 = C + (size_t)r0 * N + n0 + tcol * 8;
        float* c1 = c0 + N;
        float4 x0 = make_float4(v[0].x + bsv[0], v[1].x + bsv[1],
                                v[2].x + bsv[2], v[3].x + bsv[3]);
        float4 x1 = make_float4(v[4].x + bsv[4], v[5].x + bsv[5],
                                v[6].x + bsv[6], v[7].x + bsv[7]);
        float4 y0 = make_float4(v[0].y + bsv[0], v[1].y + bsv[1],
                                v[2].y + bsv[2], v[3].y + bsv[3]);
        float4 y1 = make_float4(v[4].y + bsv[4], v[5].y + bsv[5],
                                v[6].y + bsv[6], v[7].y + bsv[7]);
        *reinterpret_cast<float4*>(c0)     = x0;
        *reinterpret_cast<float4*>(c0 + 4) = x1;
        *reinterpret_cast<float4*>(c1)     = y0;
        *reinterpret_cast<float4*>(c1 + 4) = y1;
    }
}

// ---------------------------------------------------------------------------
// One LSTM time step, both directions, gate-interleaved weights.
// B tile pre-duplicated as f32x2 pairs, split into two 16B-stride arrays so
// both inner-loop LDS.128 are bank-conflict-free.
// Epilogue writes h (fp32) and hcat as split-bf16 (g_Ahi/g_Alo).
// ---------------------------------------------------------------------------
__global__ __launch_bounds__(256) void lstm_step_kernel(
    const int* __restrict__ tokens, int t)
{
    __shared__ float As[16][64];                  // h tile  [k][row]
    __shared__ unsigned long long Bs2a[16][32];   // dup cols 4t,4t+1
    __shared__ unsigned long long Bs2b[16][32];   // dup cols 4t+2,4t+3
    __shared__ int   toks[64];

    const int tid = threadIdx.x;
    const int dir = blockIdx.z;
    const int c0  = blockIdx.x * 64;
    const int b0  = blockIdx.y * 64;

    const float* U    = dir ? g_Utb    : g_Utf;
    const float* embW = dir ? g_embWtb : g_embWtf;
    const int s = dir ? (Sq - 1 - t) : t;

    const float* hprev = &g_h[t & 1][dir][0];
    float*       hnext = &g_h[(t + 1) & 1][dir][0];
    float*       cptr  = &g_c[dir][0];

    if (tid < 64) toks[tid] = tokens[(b0 + tid) * Sq + s];

    const int a_kq = tid & 3;
    const int a_r  = tid >> 2;
    const int b_c4 = tid & 15;
    const int b_k  = tid >> 4;

    const int trow = tid >> 4;
    const int tcol = tid & 15;

    unsigned long long acc[2][4];
#pragma unroll
    for (int p = 0; p < 2; p++)
#pragma unroll
        for (int g = 0; g < 4; g++) acc[p][g] = 0ull;

    float4 pa, pb;
    pa = *reinterpret_cast<const float4*>(&hprev[(b0 + a_r) * Hq + a_kq * 4]);
    pb = *reinterpret_cast<const float4*>(&U[b_k * G4H + c0 + b_c4 * 4]);

    for (int kc = 0; kc < Hq; kc += 16) {
        As[a_kq * 4 + 0][a_r] = pa.x;
        As[a_kq * 4 + 1][a_r] = pa.y;
        As[a_kq * 4 + 2][a_r] = pa.z;
        As[a_kq * 4 + 3][a_r] = pa.w;
        {
            ulonglong2 v01, v23;
            v01.x = dup2(pb.x); v01.y = dup2(pb.y);
            v23.x = dup2(pb.z); v23.y = dup2(pb.w);
            *reinterpret_cast<ulonglong2*>(&Bs2a[b_k][b_c4 * 2]) = v01;
            *reinterpret_cast<ulonglong2*>(&Bs2b[b_k][b_c4 * 2]) = v23;
        }
        __syncthreads();

        const int kn = kc + 16;
        if (kn < Hq) {
            pa = *reinterpret_cast<const float4*>(&hprev[(b0 + a_r) * Hq + kn + a_kq * 4]);
            pb = *reinterpret_cast<const float4*>(&U[(kn + b_k) * G4H + c0 + b_c4 * 4]);
        }

#pragma unroll
        for (int k = 0; k < 16; k++) {
            ulonglong2 a2 =
                *reinterpret_cast<const ulonglong2*>(&As[k][trow * 4]);
            ulonglong2 b01 =
                *reinterpret_cast<const ulonglong2*>(&Bs2a[k][tcol * 2]);
            ulonglong2 b23 =
                *reinterpret_cast<const ulonglong2*>(&Bs2b[k][tcol * 2]);
            ffma2(acc[0][0], a2.x, b01.x); ffma2(acc[1][0], a2.y, b01.x);
            ffma2(acc[0][1], a2.x, b01.y); ffma2(acc[1][1], a2.y, b01.y);
            ffma2(acc[0][2], a2.x, b23.x); ffma2(acc[1][2], a2.y, b23.x);
            ffma2(acc[0][3], a2.x, b23.y); ffma2(acc[1][3], a2.y, b23.y);
        }
        __syncthreads();
    }

    const int j = (c0 >> 2) + tcol;

#pragma unroll
    for (int p = 0; p < 2; p++) {
        float2 vi = unpack2(acc[p][0]);
        float2 vf = unpack2(acc[p][1]);
        float2 vg = unpack2(acc[p][2]);
        float2 vo = unpack2(acc[p][3]);
#pragma unroll
        for (int h2 = 0; h2 < 2; h2++) {
            int r = trow * 4 + p * 2 + h2;
            float zi = h2 ? vi.y : vi.x;
            float zf = h2 ? vf.y : vf.x;
            float zg = h2 ? vg.y : vg.x;
            float zo = h2 ? vo.y : vo.x;

            int tok = toks[r];
            float4 ew = *reinterpret_cast<const float4*>(&embW[(size_t)tok * G4H + (j << 2)]);
            zi += ew.x; zf += ew.y; zg += ew.z; zo += ew.w;

            float ig = sigmoidf_fast(zi);
            float fg = sigmoidf_fast(zf);
            float og = sigmoidf_fast(zo);
            float gg = dir ? fmaxf(zg, 0.f) : tanhf(zg);

            int ci = (b0 + r) * Hq + j;
            float c = fg * cptr[ci] + ig * gg;
            cptr[ci] = c;
            float hc = dir ? fmaxf(c, 0.f) : tanhf(c);
            float hv = og * hc;
            hnext[ci] = hv;

            size_t m = (size_t)(b0 + r) * Sq + s;
            size_t ao = m * Kout + dir * Hq + j;
            __nv_bfloat16 hi = __float2bfloat16(hv);
            g_Ahi[ao] = hi;
            g_Alo[ao] = __float2bfloat16(hv - __bfloat162float(hi));
        }
    }
}

// ---------------------------------------------------------------------------
// Output GEMM via HMMA (mma.sync m16n8k16 bf16) split-bf16, 3 passes:
//   out[m][n] = sum_k (Ahi*Bhi + Ahi*Blo + Alo*Bhi) + bd[n]
// CTA tile 128x128, BK=32, warps 2(m) x 4(n), warp tile 64x32.
// SMEM tiles 128 rows x 32 bf16, row stride 80B (ldmatrix conflict-free).
// cp.async 2-stage pipeline. Grid (Vq/128=16, Mout/128=256), 256 threads.
// ---------------------------------------------------------------------------
#define OG_BK       32
#define OG_CHUNKS   (Kout / OG_BK)      // 64
#define OG_RSTRIDE  80                  // bytes per 32-bf16 row (padded)
#define OG_TILE_B   (128 * OG_RSTRIDE)  // 10240
#define OG_STAGE_B  (4 * OG_TILE_B)     // Ahi, Alo, Bhi, Blo
#define OG_SMEM     (2 * OG_STAGE_B)    // 81920

__global__ __launch_bounds__(256) void out_gemm_kernel(
    const __nv_bfloat16* __restrict__ Ahi, const __nv_bfloat16* __restrict__ Alo,
    const __nv_bfloat16* __restrict__ Bhi, const __nv_bfloat16* __restrict__ Blo,
    const float* __restrict__ bd, float* __restrict__ out)
{
    extern __shared__ char smem[];
    const unsigned sb = smem_to_u32(smem);
    const int tid = threadIdx.x;
    const int wid = tid >> 5;
    const int lane = tid & 31;
    const int warp_m = wid >> 2;        // 0..1
    const int warp_n = wid & 3;         // 0..3
    const int n0 = blockIdx.x * 128;
    const int m0 = blockIdx.y * 128;

    const __nv_bfloat16* srcs[4] = {Ahi, Alo, Bhi, Blo};
    const int rowbase[4] = {m0, m0, n0, n0};

    auto issue_chunk = [&](int kc, int buf) {
        const unsigned bb = sb + buf * OG_STAGE_B;
#pragma unroll
        for (int i = 0; i < 8; i++) {
            int id   = i * 256 + tid;
            int tile = id >> 9;          // 0..3
            int rem  = id & 511;
            int r    = rem >> 2;         // 0..127
            int ch   = rem & 3;          // 16B chunk within row
            unsigned dst = bb + tile * OG_TILE_B + r * OG_RSTRIDE + ch * 16;
            const void* g = srcs[tile] +
                            (size_t)(rowbase[tile] + r) * Kout + kc + ch * 8;
            cp_async16(dst, g);
        }
        CP_COMMIT();
    };

    float acc[4][4][4];
#pragma unroll
    for (int mt = 0; mt < 4; mt++)
#pragma unroll
        for (int nt = 0; nt < 4; nt++)
#pragma unroll
            for (int q = 0; q < 4; q++) acc[mt][nt][q] = 0.f;

    issue_chunk(0, 0);
    issue_chunk(OG_BK, 1);

    for (int c = 0; c < OG_CHUNKS; c++) {
        if (c < OG_CHUNKS - 1) { CP_WAIT(1); } else { CP_WAIT(0); }
        __syncthreads();

        const unsigned bb  = sb + (c & 1) * OG_STAGE_B;
        const unsigned sAh = bb;
        const unsigned sAl = bb + OG_TILE_B;
        const unsigned sBh = bb + 2 * OG_TILE_B;
        const unsigned sBl = bb + 3 * OG_TILE_B;

#pragma unroll
        for (int kh = 0; kh < 2; kh++) {
            const int koff = kh * 32;                 // bytes (16 bf16)
            const unsigned a_off =
                (warp_m * 64 + (lane & 15)) * OG_RSTRIDE + koff + ((lane >> 4) << 4);
            const unsigned b_off =
                (warp_n * 32 + (lane & 7) + ((lane >> 4) << 3)) * OG_RSTRIDE +
                koff + (((lane >> 3) & 1) << 4);

            unsigned aH[4][4], aL[4][4], bH[4][2], bL[4][2];
#pragma unroll
            for (int mt = 0; mt < 4; mt++) {
                ldmatrix_x4(aH[mt], sAh + a_off + mt * 16 * OG_RSTRIDE);
                ldmatrix_x4(aL[mt], sAl + a_off + mt * 16 * OG_RSTRIDE);
            }
#pragma unroll
            for (int np = 0; np < 2; np++) {
                unsigned r4[4];
                ldmatrix_x4(r4, sBh + b_off + np * 16 * OG_RSTRIDE);
                bH[np * 2][0] = r4[0]; bH[np * 2][1] = r4[1];
                bH[np * 2 + 1][0] = r4[2]; bH[np * 2 + 1][1] = r4[3];
                ldmatrix_x4(r4, sBl + b_off + np * 16 * OG_RSTRIDE);
                bL[np * 2][0] = r4[0]; bL[np * 2][1] = r4[1];
                bL[np * 2 + 1][0] = r4[2]; bL[np * 2 + 1][1] = r4[3];
            }

#pragma unroll
            for (int mt = 0; mt < 4; mt++)
#pragma unroll
                for (int nt = 0; nt < 4; nt++) {
                    mma_bf16(acc[mt][nt], aH[mt], bH[nt]);
                    mma_bf16(acc[mt][nt], aH[mt], bL[nt]);
                    mma_bf16(acc[mt][nt], aL[mt], bH[nt]);
                }
        }

        __syncthreads();
        if (c + 2 < OG_CHUNKS) issue_chunk((c + 2) * OG_BK, c & 1);
    }

    // Epilogue: add bias, store fp32
#pragma unroll
    for (int mt = 0; mt < 4; mt++) {
        int r0 = m0 + warp_m * 64 + mt * 16 + (lane >> 2);
#pragma unroll
        for (int nt = 0; nt < 4; nt++) {
            int col = n0 + warp_n * 32 + nt * 8 + 2 * (lane & 3);
            float b0v = bd[col], b1v = bd[col + 1];
            float2 v0 = make_float2(acc[mt][nt][0] + b0v, acc[mt][nt][1] + b1v);
            float2 v1 = make_float2(acc[mt][nt][2] + b0v, acc[mt][nt][3] + b1v);
            *reinterpret_cast<float2*>(out + (size_t)r0 * Vq + col) = v0;
            *reinterpret_cast<float2*>(out + (size_t)(r0 + 8) * Vq + col) = v1;
        }
    }
}

// ---------------------------------------------------------------------------
// Launch
// ---------------------------------------------------------------------------
extern "C" void kernel_launch(void* const* d_in, const int* in_sizes, int n_in,
                              void* d_out, int out_size) {
    (void)in_sizes; (void)n_in; (void)out_size;
    const int*   tokens = (const int*)  d_in[0];
    const float* emb    = (const float*)d_in[1];
    const float* Wf     = (const float*)d_in[2];
    const float* Uf     = (const float*)d_in[3];
    const float* bf     = (const float*)d_in[4];
    const float* Wb     = (const float*)d_in[5];
    const float* Ub     = (const float*)d_in[6];
    const float* bb     = (const float*)d_in[7];
    const float* Wd     = (const float*)d_in[8];
    const float* bd     = (const float*)d_in[9];
    float* out = (float*)d_out;

    float *p_Wtf, *p_Wtb, *p_btf, *p_btb, *p_embWtf, *p_embWtb;
    __nv_bfloat16 *p_Ahi, *p_Alo, *p_Bhi, *p_Blo;
    cudaGetSymbolAddress((void**)&p_Wtf,    g_Wtf);
    cudaGetSymbolAddress((void**)&p_Wtb,    g_Wtb);
    cudaGetSymbolAddress((void**)&p_btf,    g_btf);
    cudaGetSymbolAddress((void**)&p_btb,    g_btb);
    cudaGetSymbolAddress((void**)&p_embWtf, g_embWtf);
    cudaGetSymbolAddress((void**)&p_embWtb, g_embWtb);
    cudaGetSymbolAddress((void**)&p_Ahi,    g_Ahi);
    cudaGetSymbolAddress((void**)&p_Alo,    g_Alo);
    cudaGetSymbolAddress((void**)&p_Bhi,    g_Bhi);
    cudaGetSymbolAddress((void**)&p_Blo,    g_Blo);

    cudaFuncSetAttribute(out_gemm_kernel,
                         cudaFuncAttributeMaxDynamicSharedMemorySize, OG_SMEM);

    init_state_kernel<<<(Bq * Hq + 255) / 256, 256>>>();
    interleave_W_kernel<<<(Eq * G4H + 255) / 256, 256>>>(Wf, Wb, bf, bb);
    interleave_U_kernel<<<(Hq * G4H + 255) / 256, 256>>>(Uf, Ub);
    split_transpose_Wd_kernel<<<dim3(Vq / 32, Kout / 32), dim3(32, 8)>>>(Wd);

    gemm_bias_kernel<<<dim3(G4H / 128, Vq / 128), 256>>>(
        emb, p_Wtf, p_btf, p_embWtf, Vq, G4H, Eq);
    gemm_bias_kernel<<<dim3(G4H / 128, Vq / 128), 256>>>(
        emb, p_Wtb, p_btb, p_embWtb, Vq, G4H, Eq);

    for (int t = 0; t < Sq; t++) {
        lstm_step_kernel<<<dim3(G4H / 64, Bq / 64, 2), 256>>>(tokens, t);
    }

    out_gemm_kernel<<<dim3(Vq / 128, Mout / 128), 256, OG_SMEM>>>(
        p_Ahi, p_Alo, p_Bhi, p_Blo, bd, out);
}

// round 7
// speedup vs baseline: 1.7098x; 1.7098x over previous
#include <cuda_runtime.h>
#include <cuda_bf16.h>
#include <math.h>

// Problem dims
#define Bq   128
#define Sq   256
#define Eq   512
#define Hq   1024
#define Vq   2048
#define G4H  4096   // 4*H
#define Kout 2048   // 2*H (output GEMM K)
#define Mout (Bq * Sq)

// ---------------------------------------------------------------------------
// Scratch (device globals; no allocation allowed)
// ---------------------------------------------------------------------------
__device__ float g_Wtf[Eq * G4H];            //  8 MB: Wf gate-interleaved
__device__ float g_Wtb[Eq * G4H];
__device__ float g_btf[G4H];
__device__ float g_btb[G4H];
__device__ float g_embWtf[Vq * G4H];         // 32 MB (bias folded)
__device__ float g_embWtb[Vq * G4H];
__device__ float g_c[2][Bq * Hq];            // [dir] cell state (fp32)
// Recurrent weights, split-bf16, gate-interleaved, TRANSPOSED: [n=j*4+g][k]
__device__ __nv_bfloat16 g_Uhif[G4H * Hq];   // 8 MB
__device__ __nv_bfloat16 g_Ulof[G4H * Hq];
__device__ __nv_bfloat16 g_Uhib[G4H * Hq];
__device__ __nv_bfloat16 g_Ulob[G4H * Hq];
// hcat as split-bf16; row m = b*S+s, col = dir*H+j. ALSO the A operand of the
// next recurrent step (rows at s_prev) and of the output GEMM.
__device__ __nv_bfloat16 g_Ahi[(size_t)Mout * Kout]; // 128 MB
__device__ __nv_bfloat16 g_Alo[(size_t)Mout * Kout]; // 128 MB
// Wd transposed + split: B[n][k] = Wd[k][n]
__device__ __nv_bfloat16 g_Bhi[Vq * Kout];   // 8 MB
__device__ __nv_bfloat16 g_Blo[Vq * Kout];   // 8 MB

// ---------------------------------------------------------------------------
// f32x2 packed-FMA helpers (embW precompute GEMM)
// ---------------------------------------------------------------------------
__device__ __forceinline__ unsigned long long dup2(float x) {
    unsigned long long r;
    asm("mov.b64 %0, {%1, %1};" : "=l"(r) : "f"(x));
    return r;
}
__device__ __forceinline__ void ffma2(unsigned long long &acc,
                                      unsigned long long a,
                                      unsigned long long b) {
    asm("fma.rn.f32x2 %0, %1, %2, %0;" : "+l"(acc) : "l"(a), "l"(b));
}
__device__ __forceinline__ float2 unpack2(unsigned long long v) {
    float2 f;
    asm("mov.b64 {%0, %1}, %2;" : "=f"(f.x), "=f"(f.y) : "l"(v));
    return f;
}
__device__ __forceinline__ float sigmoidf_fast(float x) {
    return __fdividef(1.f, 1.f + __expf(-x));
}
__device__ __forceinline__ unsigned smem_to_u32(const void* p) {
    unsigned a;
    asm("{ .reg .u64 t; cvta.to.shared.u64 t, %1; cvt.u32.u64 %0, t; }"
        : "=r"(a) : "l"(p));
    return a;
}

// ---------------------------------------------------------------------------
// sm_80+ portable async-copy + ldmatrix + HMMA
// ---------------------------------------------------------------------------
__device__ __forceinline__ void cp_async16(unsigned smem_addr, const void* gptr) {
    asm volatile("cp.async.cg.shared.global [%0], [%1], 16;"
                 :: "r"(smem_addr), "l"(gptr));
}
#define CP_COMMIT() asm volatile("cp.async.commit_group;" ::: "memory")
#define CP_WAIT(n)  asm volatile("cp.async.wait_group %0;" :: "n"(n) : "memory")

__device__ __forceinline__ void ldmatrix_x4(unsigned* r, unsigned addr) {
    asm volatile("ldmatrix.sync.aligned.m8n8.x4.shared.b16 {%0,%1,%2,%3}, [%4];"
                 : "=r"(r[0]), "=r"(r[1]), "=r"(r[2]), "=r"(r[3]) : "r"(addr));
}
__device__ __forceinline__ void mma_bf16(float* c, const unsigned* a,
                                         const unsigned* b) {
    asm volatile(
        "mma.sync.aligned.m16n8k16.row.col.f32.bf16.bf16.f32 "
        "{%0,%1,%2,%3}, {%4,%5,%6,%7}, {%8,%9}, {%0,%1,%2,%3};"
        : "+f"(c[0]), "+f"(c[1]), "+f"(c[2]), "+f"(c[3])
        : "r"(a[0]), "r"(a[1]), "r"(a[2]), "r"(a[3]), "r"(b[0]), "r"(b[1]));
}

// ---------------------------------------------------------------------------
// Zero the cell state
// ---------------------------------------------------------------------------
__global__ void init_state_kernel() {
    int i = blockIdx.x * blockDim.x + threadIdx.x;
    if (i < Bq * Hq) { g_c[0][i] = 0.f; g_c[1][i] = 0.f; }
}

// ---------------------------------------------------------------------------
// Gate-interleave W, b:  Wt[e][j*4+g] = W[e][g*H+j]
// ---------------------------------------------------------------------------
__global__ void interleave_W_kernel(const float* __restrict__ Wf,
                                    const float* __restrict__ Wb,
                                    const float* __restrict__ bf,
                                    const float* __restrict__ bb) {
    int idx = blockIdx.x * blockDim.x + threadIdx.x;
    if (idx < Eq * G4H) {
        int e = idx >> 12;
        int c = idx & 4095;
        int src = e * G4H + (c & 3) * Hq + (c >> 2);
        g_Wtf[idx] = Wf[src];
        g_Wtb[idx] = Wb[src];
    }
    if (idx < G4H) {
        int src = (idx & 3) * Hq + (idx >> 2);
        g_btf[idx] = bf[src];
        g_btb[idx] = bb[src];
    }
}

// ---------------------------------------------------------------------------
// Split + transpose + gate-interleave U:
//   Uhi/Ulo[dir][(j*4+g)][k] = split_bf16(U[k][g*H+j])
// grid (Hq/32=32 j-tiles, Hq/32=32 k-tiles, 8 = dir*4+g), block (32,8)
// ---------------------------------------------------------------------------
__global__ void split_transpose_U_kernel(const float* __restrict__ Uf,
                                         const float* __restrict__ Ub) {
    __shared__ float ts[32][33];
    int j0 = blockIdx.x * 32;
    int k0 = blockIdx.y * 32;
    int g   = blockIdx.z & 3;
    int dir = blockIdx.z >> 2;
    const float* U = dir ? Ub : Uf;
    __nv_bfloat16* Dhi = dir ? g_Uhib : g_Uhif;
    __nv_bfloat16* Dlo = dir ? g_Ulob : g_Ulof;
    int tx = threadIdx.x, ty = threadIdx.y;
#pragma unroll
    for (int i = 0; i < 32; i += 8)
        ts[ty + i][tx] = U[(size_t)(k0 + ty + i) * G4H + g * Hq + j0 + tx];
    __syncthreads();
#pragma unroll
    for (int i = 0; i < 32; i += 8) {
        int j = j0 + ty + i;
        float v = ts[tx][ty + i];          // U[k0+tx][g*H + j]
        __nv_bfloat16 hi = __float2bfloat16(v);
        float rem = v - __bfloat162float(hi);
        size_t o = (size_t)((j << 2) + g) * Hq + k0 + tx;
        Dhi[o] = hi;
        Dlo[o] = __float2bfloat16(rem);
    }
}

// ---------------------------------------------------------------------------
// Transpose + split Wd:  Bhi/Blo[n][k] = split_bf16(Wd[k][n])
// ---------------------------------------------------------------------------
__global__ void split_transpose_Wd_kernel(const float* __restrict__ Wd) {
    __shared__ float ts[32][33];
    int n0 = blockIdx.x * 32;
    int k0 = blockIdx.y * 32;
    int tx = threadIdx.x, ty = threadIdx.y;
#pragma unroll
    for (int i = 0; i < 32; i += 8)
        ts[ty + i][tx] = Wd[(size_t)(k0 + ty + i) * Vq + n0 + tx];
    __syncthreads();
#pragma unroll
    for (int i = 0; i < 32; i += 8) {
        float v = ts[tx][ty + i];            // Wd[k0+tx][n0+ty+i]
        __nv_bfloat16 hi = __float2bfloat16(v);
        float rem = v - __bfloat162float(hi);
        size_t o = (size_t)(n0 + ty + i) * Kout + k0 + tx;
        g_Bhi[o] = hi;
        g_Blo[o] = __float2bfloat16(rem);
    }
}

// ---------------------------------------------------------------------------
// Generic tiled fp32 GEMM (embW precompute):  C = A @ B + bias
// ---------------------------------------------------------------------------
__global__ __launch_bounds__(256) void gemm_bias_kernel(
    const float* __restrict__ A, const float* __restrict__ B,
    const float* __restrict__ bias, float* __restrict__ C,
    int M, int N, int K)
{
    __shared__ float As[16][128];
    __shared__ float Bs[16][128];

    const int tid = threadIdx.x;
    const int n0  = blockIdx.x * 128;
    const int m0  = blockIdx.y * 128;

    const int a_kq = tid & 3;
    const int a_r  = tid >> 2;
    const int b_c4 = tid & 31;
    const int b_k  = tid >> 5;

    const int trow = tid >> 4;
    const int tcol = tid & 15;

    unsigned long long acc[4][8];
#pragma unroll
    for (int i = 0; i < 4; i++)
#pragma unroll
        for (int j = 0; j < 8; j++) acc[i][j] = 0ull;

    float4 pa0, pa1, pb0, pb1;
    pa0 = *reinterpret_cast<const float4*>(&A[(m0 + a_r)      * K + a_kq * 4]);
    pa1 = *reinterpret_cast<const float4*>(&A[(m0 + a_r + 64) * K + a_kq * 4]);
    pb0 = *reinterpret_cast<const float4*>(&B[(b_k)     * N + n0 + b_c4 * 4]);
    pb1 = *reinterpret_cast<const float4*>(&B[(b_k + 8) * N + n0 + b_c4 * 4]);

    for (int kc = 0; kc < K; kc += 16) {
        As[a_kq * 4 + 0][a_r] = pa0.x;
        As[a_kq * 4 + 1][a_r] = pa0.y;
        As[a_kq * 4 + 2][a_r] = pa0.z;
        As[a_kq * 4 + 3][a_r] = pa0.w;
        As[a_kq * 4 + 0][a_r + 64] = pa1.x;
        As[a_kq * 4 + 1][a_r + 64] = pa1.y;
        As[a_kq * 4 + 2][a_r + 64] = pa1.z;
        As[a_kq * 4 + 3][a_r + 64] = pa1.w;
        *reinterpret_cast<float4*>(&Bs[b_k][b_c4 * 4])     = pb0;
        *reinterpret_cast<float4*>(&Bs[b_k + 8][b_c4 * 4]) = pb1;
        __syncthreads();

        const int kn = kc + 16;
        if (kn < K) {
            pa0 = *reinterpret_cast<const float4*>(&A[(m0 + a_r)      * K + kn + a_kq * 4]);
            pa1 = *reinterpret_cast<const float4*>(&A[(m0 + a_r + 64) * K + kn + a_kq * 4]);
            pb0 = *reinterpret_cast<const float4*>(&B[(kn + b_k)     * N + n0 + b_c4 * 4]);
            pb1 = *reinterpret_cast<const float4*>(&B[(kn + b_k + 8) * N + n0 + b_c4 * 4]);
        }

#pragma unroll
        for (int k = 0; k < 16; k++) {
            const ulonglong2* ap =
                reinterpret_cast<const ulonglong2*>(&As[k][trow * 8]);
            ulonglong2 av0 = ap[0];
            ulonglong2 av1 = ap[1];
            unsigned long long a4[4] = {av0.x, av0.y, av1.x, av1.y};

            float4 bv0 = *reinterpret_cast<const float4*>(&Bs[k][tcol * 8]);
            float4 bv1 = *reinterpret_cast<const float4*>(&Bs[k][tcol * 8 + 4]);
            unsigned long long bd[8];
            bd[0] = dup2(bv0.x); bd[1] = dup2(bv0.y);
            bd[2] = dup2(bv0.z); bd[3] = dup2(bv0.w);
            bd[4] = dup2(bv1.x); bd[5] = dup2(bv1.y);
            bd[6] = dup2(bv1.z); bd[7] = dup2(bv1.w);

#pragma unroll
            for (int ip = 0; ip < 4; ip++)
#pragma unroll
                for (int j = 0; j < 8; j++)
                    ffma2(acc[ip][j], a4[ip], bd[j]);
        }
        __syncthreads();
    }

    float bsv[8];
#pragma unroll
    for (int j = 0; j < 8; j++) bsv[j] = bias[n0 + tcol * 8 + j];

#pragma unroll
    for (int ip = 0; ip < 4; ip++) {
        float2 v[8];
#pragma unroll
        for (int j = 0; j < 8; j++) v[j] = unpack2(acc[ip][j]);
        int r0 = m0 + trow * 8 + ip * 2;
        float* c0 = C + (size_t)r0 * N + n0 + tcol * 8;
        float* c1 = c0 + N;
        float4 x0 = make_float4(v[0].x + bsv[0], v[1].x + bsv[1],
                                v[2].x + bsv[2], v[3].x + bsv[3]);
        float4 x1 = make_float4(v[4].x + bsv[4], v[5].x + bsv[5],
                                v[6].x + bsv[6], v[7].x + bsv[7]);
        float4 y0 = make_float4(v[0].y + bsv[0], v[1].y + bsv[1],
                                v[2].y + bsv[2], v[3].y + bsv[3]);
        float4 y1 = make_float4(v[4].y + bsv[4], v[5].y + bsv[5],
                                v[6].y + bsv[6], v[7].y + bsv[7]);
        *reinterpret_cast<float4*>(c0)     = x0;
        *reinterpret_cast<float4*>(c0 + 4) = x1;
        *reinterpret_cast<float4*>(c1)     = y0;
        *reinterpret_cast<float4*>(c1 + 4) = y1;
    }
}

// ---------------------------------------------------------------------------
// One LSTM step via HMMA split-bf16.
//   z[64 x 128cols] = h_prev[64 x 1024] @ Ut[128cols x 1024]^T  (3-pass split)
// A operand = previous step's rows of g_Ahi/g_Alo (cols dir*H..dir*H+1023).
// CTA tile 64 batch x 128 interleaved cols (= 32 hidden units x 4 gates).
// Grid (G4H/128=32, Bq/64=2, dir=2) = 128 CTAs, 256 threads, warps 2m x 4n.
// After the GEMM, frags -> SMEM z-tile -> fused gate update (embW gather),
// writing c (fp32) and h as split-bf16 into g_Ahi/g_Alo at position s.
// ---------------------------------------------------------------------------
#define LS_RS     80                       // bytes per 32-bf16 SMEM row
#define LS_ATILE  (64 * LS_RS)             // 5120
#define LS_BTILE  (128 * LS_RS)            // 10240
#define LS_STAGE  (2 * LS_ATILE + 2 * LS_BTILE)  // 30720
#define LS_SMEM   (2 * LS_STAGE)           // 61440 (z-tile aliases this)

__global__ __launch_bounds__(256, 1) void lstm_mma_step_kernel(
    const int* __restrict__ tokens, int t)
{
    extern __shared__ char smem[];
    const unsigned sb = smem_to_u32(smem);
    float (*zs)[132] = reinterpret_cast<float (*)[132]>(smem);  // 64x132 fp32
    __shared__ int toks[64];

    const int tid = threadIdx.x;
    const int wid = tid >> 5;
    const int lane = tid & 31;
    const int warp_m = wid >> 2;        // 0..1
    const int warp_n = wid & 3;         // 0..3
    const int c0  = blockIdx.x * 128;   // interleaved col base
    const int b0  = blockIdx.y * 64;
    const int dir = blockIdx.z;
    const int s  = dir ? (Sq - 1 - t) : t;
    const int sp = dir ? (Sq - t) : (t - 1);   // previous step's s (t>0)

    const __nv_bfloat16* Uhi = dir ? g_Uhib : g_Uhif;
    const __nv_bfloat16* Ulo = dir ? g_Ulob : g_Ulof;

    if (tid < 64) toks[tid] = tokens[(b0 + tid) * Sq + s];

    float acc[2][4][4];
#pragma unroll
    for (int mt = 0; mt < 2; mt++)
#pragma unroll
        for (int nt = 0; nt < 4; nt++)
#pragma unroll
            for (int q = 0; q < 4; q++) acc[mt][nt][q] = 0.f;

    if (t > 0) {
        auto issue_chunk = [&](int kc, int buf) {
            const unsigned bb = sb + buf * LS_STAGE;
#pragma unroll
            for (int i = 0; i < 6; i++) {
                int id = i * 256 + tid;            // 0..1535
                if (id < 512) {
                    int part = id >> 8;            // 0 = Ahi, 1 = Alo
                    int rem = id & 255;
                    int r = rem >> 2, ch = rem & 3;
                    const __nv_bfloat16* src = part ? g_Alo : g_Ahi;
                    unsigned dst = bb + part * LS_ATILE + r * LS_RS + ch * 16;
                    cp_async16(dst, src +
                        ((size_t)(b0 + r) * Sq + sp) * Kout + dir * Hq + kc + ch * 8);
                } else {
                    int id2 = id - 512;            // 0..1023
                    int part = id2 >> 9;           // 0 = Uhi, 1 = Ulo
                    int rem = id2 & 511;
                    int r = rem >> 2, ch = rem & 3;
                    const __nv_bfloat16* src = part ? Ulo : Uhi;
                    unsigned dst = bb + 2 * LS_ATILE + part * LS_BTILE +
                                   r * LS_RS + ch * 16;
                    cp_async16(dst, src + (size_t)(c0 + r) * Hq + kc + ch * 8);
                }
            }
            CP_COMMIT();
        };

        issue_chunk(0, 0);
        issue_chunk(32, 1);

        for (int c = 0; c < 32; c++) {
            if (c < 31) { CP_WAIT(1); } else { CP_WAIT(0); }
            __syncthreads();

            const unsigned bb  = sb + (c & 1) * LS_STAGE;
            const unsigned sAh = bb;
            const unsigned sAl = bb + LS_ATILE;
            const unsigned sBh = bb + 2 * LS_ATILE;
            const unsigned sBl = bb + 2 * LS_ATILE + LS_BTILE;

#pragma unroll
            for (int kh = 0; kh < 2; kh++) {
                const int koff = kh * 32;          // bytes (16 bf16)
                const unsigned a_off =
                    (warp_m * 32 + (lane & 15)) * LS_RS + koff + ((lane >> 4) << 4);
                const unsigned b_off =
                    (warp_n * 32 + (lane & 7) + ((lane >> 4) << 3)) * LS_RS +
                    koff + (((lane >> 3) & 1) << 4);

                unsigned aH[2][4], aL[2][4], bH[4][2], bL[4][2];
#pragma unroll
                for (int mt = 0; mt < 2; mt++) {
                    ldmatrix_x4(aH[mt], sAh + a_off + mt * 16 * LS_RS);
                    ldmatrix_x4(aL[mt], sAl + a_off + mt * 16 * LS_RS);
                }
#pragma unroll
                for (int np = 0; np < 2; np++) {
                    unsigned r4[4];
                    ldmatrix_x4(r4, sBh + b_off + np * 16 * LS_RS);
                    bH[np * 2][0] = r4[0]; bH[np * 2][1] = r4[1];
                    bH[np * 2 + 1][0] = r4[2]; bH[np * 2 + 1][1] = r4[3];
                    ldmatrix_x4(r4, sBl + b_off + np * 16 * LS_RS);
                    bL[np * 2][0] = r4[0]; bL[np * 2][1] = r4[1];
                    bL[np * 2 + 1][0] = r4[2]; bL[np * 2 + 1][1] = r4[3];
                }

#pragma unroll
                for (int mt = 0; mt < 2; mt++)
#pragma unroll
                    for (int nt = 0; nt < 4; nt++) {
                        mma_bf16(acc[mt][nt], aH[mt], bH[nt]);
                        mma_bf16(acc[mt][nt], aH[mt], bL[nt]);
                        mma_bf16(acc[mt][nt], aL[mt], bH[nt]);
                    }
            }

            __syncthreads();
            if (c + 2 < 32) issue_chunk((c + 2) * 32, c & 1);
        }
    }

    __syncthreads();   // all MMA reads done; safe to alias stage smem as zs

    // fragments -> z tile
#pragma unroll
    for (int mt = 0; mt < 2; mt++) {
        int r = warp_m * 32 + mt * 16 + (lane >> 2);
#pragma unroll
        for (int nt = 0; nt < 4; nt++) {
            int col = warp_n * 32 + nt * 8 + 2 * (lane & 3);
            *reinterpret_cast<float2*>(&zs[r][col]) =
                make_float2(acc[mt][nt][0], acc[mt][nt][1]);
            *reinterpret_cast<float2*>(&zs[r + 8][col]) =
                make_float2(acc[mt][nt][2], acc[mt][nt][3]);
        }
    }
    __syncthreads();

    // fused gate update: 64 rows x 32 hidden units
    const float* embW = dir ? g_embWtb : g_embWtf;
    float* cptr = &g_c[dir][0];
    const int j0q = c0 >> 2;

#pragma unroll
    for (int it = 0; it < 8; it++) {
        int idx = it * 256 + tid;
        int r  = idx >> 5;     // 0..63
        int jj = idx & 31;     // 0..31
        int j = j0q + jj;

        float4 z4 = *reinterpret_cast<const float4*>(&zs[r][jj * 4]);
        int tok = toks[r];
        float4 ew = *reinterpret_cast<const float4*>(
            &embW[(size_t)tok * G4H + (j << 2)]);
        float zi = z4.x + ew.x;
        float zf = z4.y + ew.y;
        float zg = z4.z + ew.z;
        float zo = z4.w + ew.w;

        float ig = sigmoidf_fast(zi);
        float fg = sigmoidf_fast(zf);
        float og = sigmoidf_fast(zo);
        float gg = dir ? fmaxf(zg, 0.f) : tanhf(zg);

        int ci = (b0 + r) * Hq + j;
        float cv = fg * cptr[ci] + ig * gg;
        cptr[ci] = cv;
        float hc = dir ? fmaxf(cv, 0.f) : tanhf(cv);
        float hv = og * hc;

        size_t ao = ((size_t)(b0 + r) * Sq + s) * Kout + dir * Hq + j;
        __nv_bfloat16 hi = __float2bfloat16(hv);
        g_Ahi[ao] = hi;
        g_Alo[ao] = __float2bfloat16(hv - __bfloat162float(hi));
    }
}

// ---------------------------------------------------------------------------
// Output GEMM via HMMA split-bf16 (validated in R5):
//   out[m][n] = Ahi*Bhi + Ahi*Blo + Alo*Bhi + bd[n]
// ---------------------------------------------------------------------------
#define OG_BK       32
#define OG_CHUNKS   (Kout / OG_BK)      // 64
#define OG_RSTRIDE  80
#define OG_TILE_B   (128 * OG_RSTRIDE)  // 10240
#define OG_STAGE_B  (4 * OG_TILE_B)
#define OG_SMEM     (2 * OG_STAGE_B)    // 81920

__global__ __launch_bounds__(256) void out_gemm_kernel(
    const __nv_bfloat16* __restrict__ Ahi, const __nv_bfloat16* __restrict__ Alo,
    const __nv_bfloat16* __restrict__ Bhi, const __nv_bfloat16* __restrict__ Blo,
    const float* __restrict__ bd, float* __restrict__ out)
{
    extern __shared__ char smem[];
    const unsigned sb = smem_to_u32(smem);
    const int tid = threadIdx.x;
    const int wid = tid >> 5;
    const int lane = tid & 31;
    const int warp_m = wid >> 2;
    const int warp_n = wid & 3;
    const int n0 = blockIdx.x * 128;
    const int m0 = blockIdx.y * 128;

    const __nv_bfloat16* srcs[4] = {Ahi, Alo, Bhi, Blo};
    const int rowbase[4] = {m0, m0, n0, n0};

    auto issue_chunk = [&](int kc, int buf) {
        const unsigned bb = sb + buf * OG_STAGE_B;
#pragma unroll
        for (int i = 0; i < 8; i++) {
            int id   = i * 256 + tid;
            int tile = id >> 9;
            int rem  = id & 511;
            int r    = rem >> 2;
            int ch   = rem & 3;
            unsigned dst = bb + tile * OG_TILE_B + r * OG_RSTRIDE + ch * 16;
            const void* g = srcs[tile] +
                            (size_t)(rowbase[tile] + r) * Kout + kc + ch * 8;
            cp_async16(dst, g);
        }
        CP_COMMIT();
    };

    float acc[4][4][4];
#pragma unroll
    for (int mt = 0; mt < 4; mt++)
#pragma unroll
        for (int nt = 0; nt < 4; nt++)
#pragma unroll
            for (int q = 0; q < 4; q++) acc[mt][nt][q] = 0.f;

    issue_chunk(0, 0);
    issue_chunk(OG_BK, 1);

    for (int c = 0; c < OG_CHUNKS; c++) {
        if (c < OG_CHUNKS - 1) { CP_WAIT(1); } else { CP_WAIT(0); }
        __syncthreads();

        const unsigned bb  = sb + (c & 1) * OG_STAGE_B;
        const unsigned sAh = bb;
        const unsigned sAl = bb + OG_TILE_B;
        const unsigned sBh = bb + 2 * OG_TILE_B;
        const unsigned sBl = bb + 3 * OG_TILE_B;

#pragma unroll
        for (int kh = 0; kh < 2; kh++) {
            const int koff = kh * 32;
            const unsigned a_off =
                (warp_m * 64 + (lane & 15)) * OG_RSTRIDE + koff + ((lane >> 4) << 4);
            const unsigned b_off =
                (warp_n * 32 + (lane & 7) + ((lane >> 4) << 3)) * OG_RSTRIDE +
                koff + (((lane >> 3) & 1) << 4);

            unsigned aH[4][4], aL[4][4], bH[4][2], bL[4][2];
#pragma unroll
            for (int mt = 0; mt < 4; mt++) {
                ldmatrix_x4(aH[mt], sAh + a_off + mt * 16 * OG_RSTRIDE);
                ldmatrix_x4(aL[mt], sAl + a_off + mt * 16 * OG_RSTRIDE);
            }
#pragma unroll
            for (int np = 0; np < 2; np++) {
                unsigned r4[4];
                ldmatrix_x4(r4, sBh + b_off + np * 16 * OG_RSTRIDE);
                bH[np * 2][0] = r4[0]; bH[np * 2][1] = r4[1];
                bH[np * 2 + 1][0] = r4[2]; bH[np * 2 + 1][1] = r4[3];
                ldmatrix_x4(r4, sBl + b_off + np * 16 * OG_RSTRIDE);
                bL[np * 2][0] = r4[0]; bL[np * 2][1] = r4[1];
                bL[np * 2 + 1][0] = r4[2]; bL[np * 2 + 1][1] = r4[3];
            }

#pragma unroll
            for (int mt = 0; mt < 4; mt++)
#pragma unroll
                for (int nt = 0; nt < 4; nt++) {
                    mma_bf16(acc[mt][nt], aH[mt], bH[nt]);
                    mma_bf16(acc[mt][nt], aH[mt], bL[nt]);
                    mma_bf16(acc[mt][nt], aL[mt], bH[nt]);
                }
        }

        __syncthreads();
        if (c + 2 < OG_CHUNKS) issue_chunk((c + 2) * OG_BK, c & 1);
    }

#pragma unroll
    for (int mt = 0; mt < 4; mt++) {
        int r0 = m0 + warp_m * 64 + mt * 16 + (lane >> 2);
#pragma unroll
        for (int nt = 0; nt < 4; nt++) {
            int col = n0 + warp_n * 32 + nt * 8 + 2 * (lane & 3);
            float b0v = bd[col], b1v = bd[col + 1];
            float2 v0 = make_float2(acc[mt][nt][0] + b0v, acc[mt][nt][1] + b1v);
            float2 v1 = make_float2(acc[mt][nt][2] + b0v, acc[mt][nt][3] + b1v);
            *reinterpret_cast<float2*>(out + (size_t)r0 * Vq + col) = v0;
            *reinterpret_cast<float2*>(out + (size_t)(r0 + 8) * Vq + col) = v1;
        }
    }
}

// ---------------------------------------------------------------------------
// Launch
// ---------------------------------------------------------------------------
extern "C" void kernel_launch(void* const* d_in, const int* in_sizes, int n_in,
                              void* d_out, int out_size) {
    (void)in_sizes; (void)n_in; (void)out_size;
    const int*   tokens = (const int*)  d_in[0];
    const float* emb    = (const float*)d_in[1];
    const float* Wf     = (const float*)d_in[2];
    const float* Uf     = (const float*)d_in[3];
    const float* bf     = (const float*)d_in[4];
    const float* Wb     = (const float*)d_in[5];
    const float* Ub     = (const float*)d_in[6];
    const float* bb     = (const float*)d_in[7];
    const float* Wd     = (const float*)d_in[8];
    const float* bd     = (const float*)d_in[9];
    float* out = (float*)d_out;

    float *p_Wtf, *p_Wtb, *p_btf, *p_btb, *p_embWtf, *p_embWtb;
    __nv_bfloat16 *p_Ahi, *p_Alo, *p_Bhi, *p_Blo;
    cudaGetSymbolAddress((void**)&p_Wtf,    g_Wtf);
    cudaGetSymbolAddress((void**)&p_Wtb,    g_Wtb);
    cudaGetSymbolAddress((void**)&p_btf,    g_btf);
    cudaGetSymbolAddress((void**)&p_btb,    g_btb);
    cudaGetSymbolAddress((void**)&p_embWtf, g_embWtf);
    cudaGetSymbolAddress((void**)&p_embWtb, g_embWtb);
    cudaGetSymbolAddress((void**)&p_Ahi,    g_Ahi);
    cudaGetSymbolAddress((void**)&p_Alo,    g_Alo);
    cudaGetSymbolAddress((void**)&p_Bhi,    g_Bhi);
    cudaGetSymbolAddress((void**)&p_Blo,    g_Blo);

    cudaFuncSetAttribute(out_gemm_kernel,
                         cudaFuncAttributeMaxDynamicSharedMemorySize, OG_SMEM);
    cudaFuncSetAttribute(lstm_mma_step_kernel,
                         cudaFuncAttributeMaxDynamicSharedMemorySize, LS_SMEM);

    init_state_kernel<<<(Bq * Hq + 255) / 256, 256>>>();
    interleave_W_kernel<<<(Eq * G4H + 255) / 256, 256>>>(Wf, Wb, bf, bb);
    split_transpose_U_kernel<<<dim3(Hq / 32, Hq / 32, 8), dim3(32, 8)>>>(Uf, Ub);
    split_transpose_Wd_kernel<<<dim3(Vq / 32, Kout / 32), dim3(32, 8)>>>(Wd);

    // embWt = emb @ Wt + bt  (gate-interleaved, bias folded)
    gemm_bias_kernel<<<dim3(G4H / 128, Vq / 128), 256>>>(
        emb, p_Wtf, p_btf, p_embWtf, Vq, G4H, Eq);
    gemm_bias_kernel<<<dim3(G4H / 128, Vq / 128), 256>>>(
        emb, p_Wtb, p_btb, p_embWtb, Vq, G4H, Eq);

    // 256 sequential recurrent steps (both directions per launch), HMMA
    for (int t = 0; t < Sq; t++) {
        lstm_mma_step_kernel<<<dim3(G4H / 128, Bq / 64, 2), 256, LS_SMEM>>>(
            tokens, t);
    }

    out_gemm_kernel<<<dim3(Vq / 128, Mout / 128), 256, OG_SMEM>>>(
        p_Ahi, p_Alo, p_Bhi, p_Blo, bd, out);
}

// round 8
// speedup vs baseline: 2.6622x; 1.5571x over previous
#include <cuda_runtime.h>
#include <cuda_bf16.h>
#include <math.h>

// Problem dims
#define Bq   128
#define Sq   256
#define Eq   512
#define Hq   1024
#define Vq   2048
#define G4H  4096   // 4*H
#define Kout 2048   // 2*H (output GEMM K)
#define Mout (Bq * Sq)

// ---------------------------------------------------------------------------
// Scratch (device globals; no allocation allowed)
// ---------------------------------------------------------------------------
__device__ float g_Wtf[Eq * G4H];            //  8 MB: Wf gate-interleaved
__device__ float g_Wtb[Eq * G4H];
__device__ float g_btf[G4H];
__device__ float g_btb[G4H];
__device__ float g_embWtf[Vq * G4H];         // 32 MB (bias folded)
__device__ float g_embWtb[Vq * G4H];
__device__ float g_c[2][Bq * Hq];            // [dir] cell state (fp32)
// Recurrent weights, split-bf16, gate-interleaved, TRANSPOSED: [n=j*4+g][k]
__device__ __nv_bfloat16 g_Uhif[G4H * Hq];   // 8 MB
__device__ __nv_bfloat16 g_Ulof[G4H * Hq];
__device__ __nv_bfloat16 g_Uhib[G4H * Hq];
__device__ __nv_bfloat16 g_Ulob[G4H * Hq];
// hcat as split-bf16; row m = b*S+s, col = dir*H+j. ALSO the A operand of the
// next recurrent step (rows at s_prev) and of the output GEMM.
__device__ __nv_bfloat16 g_Ahi[(size_t)Mout * Kout]; // 128 MB
__device__ __nv_bfloat16 g_Alo[(size_t)Mout * Kout]; // 128 MB
// Wd transposed + split: B[n][k] = Wd[k][n]
__device__ __nv_bfloat16 g_Bhi[Vq * Kout];   // 8 MB
__device__ __nv_bfloat16 g_Blo[Vq * Kout];   // 8 MB

// ---------------------------------------------------------------------------
// f32x2 packed-FMA helpers (embW precompute GEMM)
// ---------------------------------------------------------------------------
__device__ __forceinline__ unsigned long long dup2(float x) {
    unsigned long long r;
    asm("mov.b64 %0, {%1, %1};" : "=l"(r) : "f"(x));
    return r;
}
__device__ __forceinline__ void ffma2(unsigned long long &acc,
                                      unsigned long long a,
                                      unsigned long long b) {
    asm("fma.rn.f32x2 %0, %1, %2, %0;" : "+l"(acc) : "l"(a), "l"(b));
}
__device__ __forceinline__ float2 unpack2(unsigned long long v) {
    float2 f;
    asm("mov.b64 {%0, %1}, %2;" : "=f"(f.x), "=f"(f.y) : "l"(v));
    return f;
}
__device__ __forceinline__ float sigmoidf_fast(float x) {
    return __fdividef(1.f, 1.f + __expf(-x));
}
__device__ __forceinline__ unsigned smem_to_u32(const void* p) {
    unsigned a;
    asm("{ .reg .u64 t; cvta.to.shared.u64 t, %1; cvt.u32.u64 %0, t; }"
        : "=r"(a) : "l"(p));
    return a;
}

// ---------------------------------------------------------------------------
// sm_80+ portable async-copy + ldmatrix + HMMA
// ---------------------------------------------------------------------------
__device__ __forceinline__ void cp_async16(unsigned smem_addr, const void* gptr) {
    asm volatile("cp.async.cg.shared.global [%0], [%1], 16;"
                 :: "r"(smem_addr), "l"(gptr));
}
#define CP_COMMIT() asm volatile("cp.async.commit_group;" ::: "memory")
#define CP_WAIT(n)  asm volatile("cp.async.wait_group %0;" :: "n"(n) : "memory")

__device__ __forceinline__ void ldmatrix_x4(unsigned* r, unsigned addr) {
    asm volatile("ldmatrix.sync.aligned.m8n8.x4.shared.b16 {%0,%1,%2,%3}, [%4];"
                 : "=r"(r[0]), "=r"(r[1]), "=r"(r[2]), "=r"(r[3]) : "r"(addr));
}
__device__ __forceinline__ void mma_bf16(float* c, const unsigned* a,
                                         const unsigned* b) {
    asm volatile(
        "mma.sync.aligned.m16n8k16.row.col.f32.bf16.bf16.f32 "
        "{%0,%1,%2,%3}, {%4,%5,%6,%7}, {%8,%9}, {%0,%1,%2,%3};"
        : "+f"(c[0]), "+f"(c[1]), "+f"(c[2]), "+f"(c[3])
        : "r"(a[0]), "r"(a[1]), "r"(a[2]), "r"(a[3]), "r"(b[0]), "r"(b[1]));
}

// ---------------------------------------------------------------------------
// Zero the cell state
// ---------------------------------------------------------------------------
__global__ void init_state_kernel() {
    int i = blockIdx.x * blockDim.x + threadIdx.x;
    if (i < Bq * Hq) { g_c[0][i] = 0.f; g_c[1][i] = 0.f; }
}

// ---------------------------------------------------------------------------
// Gate-interleave W, b:  Wt[e][j*4+g] = W[e][g*H+j]
// ---------------------------------------------------------------------------
__global__ void interleave_W_kernel(const float* __restrict__ Wf,
                                    const float* __restrict__ Wb,
                                    const float* __restrict__ bf,
                                    const float* __restrict__ bb) {
    int idx = blockIdx.x * blockDim.x + threadIdx.x;
    if (idx < Eq * G4H) {
        int e = idx >> 12;
        int c = idx & 4095;
        int src = e * G4H + (c & 3) * Hq + (c >> 2);
        g_Wtf[idx] = Wf[src];
        g_Wtb[idx] = Wb[src];
    }
    if (idx < G4H) {
        int src = (idx & 3) * Hq + (idx >> 2);
        g_btf[idx] = bf[src];
        g_btb[idx] = bb[src];
    }
}

// ---------------------------------------------------------------------------
// Split + transpose + gate-interleave U:
//   Uhi/Ulo[dir][(j*4+g)][k] = split_bf16(U[k][g*H+j])
// ---------------------------------------------------------------------------
__global__ void split_transpose_U_kernel(const float* __restrict__ Uf,
                                         const float* __restrict__ Ub) {
    __shared__ float ts[32][33];
    int j0 = blockIdx.x * 32;
    int k0 = blockIdx.y * 32;
    int g   = blockIdx.z & 3;
    int dir = blockIdx.z >> 2;
    const float* U = dir ? Ub : Uf;
    __nv_bfloat16* Dhi = dir ? g_Uhib : g_Uhif;
    __nv_bfloat16* Dlo = dir ? g_Ulob : g_Ulof;
    int tx = threadIdx.x, ty = threadIdx.y;
#pragma unroll
    for (int i = 0; i < 32; i += 8)
        ts[ty + i][tx] = U[(size_t)(k0 + ty + i) * G4H + g * Hq + j0 + tx];
    __syncthreads();
#pragma unroll
    for (int i = 0; i < 32; i += 8) {
        int j = j0 + ty + i;
        float v = ts[tx][ty + i];          // U[k0+tx][g*H + j]
        __nv_bfloat16 hi = __float2bfloat16(v);
        float rem = v - __bfloat162float(hi);
        size_t o = (size_t)((j << 2) + g) * Hq + k0 + tx;
        Dhi[o] = hi;
        Dlo[o] = __float2bfloat16(rem);
    }
}

// ---------------------------------------------------------------------------
// Transpose + split Wd:  Bhi/Blo[n][k] = split_bf16(Wd[k][n])
// ---------------------------------------------------------------------------
__global__ void split_transpose_Wd_kernel(const float* __restrict__ Wd) {
    __shared__ float ts[32][33];
    int n0 = blockIdx.x * 32;
    int k0 = blockIdx.y * 32;
    int tx = threadIdx.x, ty = threadIdx.y;
#pragma unroll
    for (int i = 0; i < 32; i += 8)
        ts[ty + i][tx] = Wd[(size_t)(k0 + ty + i) * Vq + n0 + tx];
    __syncthreads();
#pragma unroll
    for (int i = 0; i < 32; i += 8) {
        float v = ts[tx][ty + i];            // Wd[k0+tx][n0+ty+i]
        __nv_bfloat16 hi = __float2bfloat16(v);
        float rem = v - __bfloat162float(hi);
        size_t o = (size_t)(n0 + ty + i) * Kout + k0 + tx;
        g_Bhi[o] = hi;
        g_Blo[o] = __float2bfloat16(rem);
    }
}

// ---------------------------------------------------------------------------
// Generic tiled fp32 GEMM (embW precompute):  C = A @ B + bias
// ---------------------------------------------------------------------------
__global__ __launch_bounds__(256) void gemm_bias_kernel(
    const float* __restrict__ A, const float* __restrict__ B,
    const float* __restrict__ bias, float* __restrict__ C,
    int M, int N, int K)
{
    __shared__ float As[16][128];
    __shared__ float Bs[16][128];

    const int tid = threadIdx.x;
    const int n0  = blockIdx.x * 128;
    const int m0  = blockIdx.y * 128;

    const int a_kq = tid & 3;
    const int a_r  = tid >> 2;
    const int b_c4 = tid & 31;
    const int b_k  = tid >> 5;

    const int trow = tid >> 4;
    const int tcol = tid & 15;

    unsigned long long acc[4][8];
#pragma unroll
    for (int i = 0; i < 4; i++)
#pragma unroll
        for (int j = 0; j < 8; j++) acc[i][j] = 0ull;

    float4 pa0, pa1, pb0, pb1;
    pa0 = *reinterpret_cast<const float4*>(&A[(m0 + a_r)      * K + a_kq * 4]);
    pa1 = *reinterpret_cast<const float4*>(&A[(m0 + a_r + 64) * K + a_kq * 4]);
    pb0 = *reinterpret_cast<const float4*>(&B[(b_k)     * N + n0 + b_c4 * 4]);
    pb1 = *reinterpret_cast<const float4*>(&B[(b_k + 8) * N + n0 + b_c4 * 4]);

    for (int kc = 0; kc < K; kc += 16) {
        As[a_kq * 4 + 0][a_r] = pa0.x;
        As[a_kq * 4 + 1][a_r] = pa0.y;
        As[a_kq * 4 + 2][a_r] = pa0.z;
        As[a_kq * 4 + 3][a_r] = pa0.w;
        As[a_kq * 4 + 0][a_r + 64] = pa1.x;
        As[a_kq * 4 + 1][a_r + 64] = pa1.y;
        As[a_kq * 4 + 2][a_r + 64] = pa1.z;
        As[a_kq * 4 + 3][a_r + 64] = pa1.w;
        *reinterpret_cast<float4*>(&Bs[b_k][b_c4 * 4])     = pb0;
        *reinterpret_cast<float4*>(&Bs[b_k + 8][b_c4 * 4]) = pb1;
        __syncthreads();

        const int kn = kc + 16;
        if (kn < K) {
            pa0 = *reinterpret_cast<const float4*>(&A[(m0 + a_r)      * K + kn + a_kq * 4]);
            pa1 = *reinterpret_cast<const float4*>(&A[(m0 + a_r + 64) * K + kn + a_kq * 4]);
            pb0 = *reinterpret_cast<const float4*>(&B[(kn + b_k)     * N + n0 + b_c4 * 4]);
            pb1 = *reinterpret_cast<const float4*>(&B[(kn + b_k + 8) * N + n0 + b_c4 * 4]);
        }

#pragma unroll
        for (int k = 0; k < 16; k++) {
            const ulonglong2* ap =
                reinterpret_cast<const ulonglong2*>(&As[k][trow * 8]);
            ulonglong2 av0 = ap[0];
            ulonglong2 av1 = ap[1];
            unsigned long long a4[4] = {av0.x, av0.y, av1.x, av1.y};

            float4 bv0 = *reinterpret_cast<const float4*>(&Bs[k][tcol * 8]);
            float4 bv1 = *reinterpret_cast<const float4*>(&Bs[k][tcol * 8 + 4]);
            unsigned long long bd[8];
            bd[0] = dup2(bv0.x); bd[1] = dup2(bv0.y);
            bd[2] = dup2(bv0.z); bd[3] = dup2(bv0.w);
            bd[4] = dup2(bv1.x); bd[5] = dup2(bv1.y);
            bd[6] = dup2(bv1.z); bd[7] = dup2(bv1.w);

#pragma unroll
            for (int ip = 0; ip < 4; ip++)
#pragma unroll
                for (int j = 0; j < 8; j++)
                    ffma2(acc[ip][j], a4[ip], bd[j]);
        }
        __syncthreads();
    }

    float bsv[8];
#pragma unroll
    for (int j = 0; j < 8; j++) bsv[j] = bias[n0 + tcol * 8 + j];

#pragma unroll
    for (int ip = 0; ip < 4; ip++) {
        float2 v[8];
#pragma unroll
        for (int j = 0; j < 8; j++) v[j] = unpack2(acc[ip][j]);
        int r0 = m0 + trow * 8 + ip * 2;
        float* c0 = C + (size_t)r0 * N + n0 + tcol * 8;
        float* c1 = c0 + N;
        float4 x0 = make_float4(v[0].x + bsv[0], v[1].x + bsv[1],
                                v[2].x + bsv[2], v[3].x + bsv[3]);
        float4 x1 = make_float4(v[4].x + bsv[4], v[5].x + bsv[5],
                                v[6].x + bsv[6], v[7].x + bsv[7]);
        float4 y0 = make_float4(v[0].y + bsv[0], v[1].y + bsv[1],
                                v[2].y + bsv[2], v[3].y + bsv[3]);
        float4 y1 = make_float4(v[4].y + bsv[4], v[5].y + bsv[5],
                                v[6].y + bsv[6], v[7].y + bsv[7]);
        *reinterpret_cast<float4*>(c0)     = x0;
        *reinterpret_cast<float4*>(c0 + 4) = x1;
        *reinterpret_cast<float4*>(c1)     = y0;
        *reinterpret_cast<float4*>(c1 + 4) = y1;
    }
}

// ---------------------------------------------------------------------------
// One LSTM step via HMMA split-bf16 — 512 threads (16 warps, 4m x 4n).
//   z[64 x 128cols] = h_prev[64 x 1024] @ Ut[128cols x 1024]^T  (3-pass split)
// CTA tile 64 batch x 128 interleaved cols; warp tile 16 x 32.
// Grid (G4H/128=32, Bq/64=2, dir=2) = 128 CTAs.
// ---------------------------------------------------------------------------
#define LS_RS     80                       // bytes per 32-bf16 SMEM row
#define LS_ATILE  (64 * LS_RS)             // 5120
#define LS_BTILE  (128 * LS_RS)            // 10240
#define LS_STAGE  (2 * LS_ATILE + 2 * LS_BTILE)  // 30720
#define LS_SMEM   (2 * LS_STAGE)           // 61440 (z-tile aliases this)

__global__ __launch_bounds__(512, 1) void lstm_mma_step_kernel(
    const int* __restrict__ tokens, int t)
{
    extern __shared__ char smem[];
    const unsigned sb = smem_to_u32(smem);
    float (*zs)[132] = reinterpret_cast<float (*)[132]>(smem);  // 64x132 fp32
    __shared__ int toks[64];

    const int tid = threadIdx.x;
    const int wid = tid >> 5;
    const int lane = tid & 31;
    const int warp_m = wid >> 2;        // 0..3 (16 rows each)
    const int warp_n = wid & 3;         // 0..3 (32 cols each)
    const int c0  = blockIdx.x * 128;   // interleaved col base
    const int b0  = blockIdx.y * 64;
    const int dir = blockIdx.z;
    const int s  = dir ? (Sq - 1 - t) : t;
    const int sp = dir ? (Sq - t) : (t - 1);   // previous step's s (t>0)

    const __nv_bfloat16* Uhi = dir ? g_Uhib : g_Uhif;
    const __nv_bfloat16* Ulo = dir ? g_Ulob : g_Ulof;

    if (tid < 64) toks[tid] = tokens[(b0 + tid) * Sq + s];

    float acc[4][4];                    // [nt][quad]
#pragma unroll
    for (int nt = 0; nt < 4; nt++)
#pragma unroll
        for (int q = 0; q < 4; q++) acc[nt][q] = 0.f;

    if (t > 0) {
        auto issue_chunk = [&](int kc, int buf) {
            const unsigned bb = sb + buf * LS_STAGE;
#pragma unroll
            for (int i = 0; i < 3; i++) {
                int id = i * 512 + tid;            // 0..1535
                if (id < 512) {
                    int part = id >> 8;            // 0 = Ahi, 1 = Alo
                    int rem = id & 255;
                    int r = rem >> 2, ch = rem & 3;
                    const __nv_bfloat16* src = part ? g_Alo : g_Ahi;
                    unsigned dst = bb + part * LS_ATILE + r * LS_RS + ch * 16;
                    cp_async16(dst, src +
                        ((size_t)(b0 + r) * Sq + sp) * Kout + dir * Hq + kc + ch * 8);
                } else {
                    int id2 = id - 512;            // 0..1023
                    int part = id2 >> 9;           // 0 = Uhi, 1 = Ulo
                    int rem = id2 & 511;
                    int r = rem >> 2, ch = rem & 3;
                    const __nv_bfloat16* src = part ? Ulo : Uhi;
                    unsigned dst = bb + 2 * LS_ATILE + part * LS_BTILE +
                                   r * LS_RS + ch * 16;
                    cp_async16(dst, src + (size_t)(c0 + r) * Hq + kc + ch * 8);
                }
            }
            CP_COMMIT();
        };

        issue_chunk(0, 0);
        issue_chunk(32, 1);

        for (int c = 0; c < 32; c++) {
            if (c < 31) { CP_WAIT(1); } else { CP_WAIT(0); }
            __syncthreads();

            const unsigned bb  = sb + (c & 1) * LS_STAGE;
            const unsigned sAh = bb;
            const unsigned sAl = bb + LS_ATILE;
            const unsigned sBh = bb + 2 * LS_ATILE;
            const unsigned sBl = bb + 2 * LS_ATILE + LS_BTILE;

#pragma unroll
            for (int kh = 0; kh < 2; kh++) {
                const int koff = kh * 32;          // bytes (16 bf16)
                const unsigned a_off =
                    (warp_m * 16 + (lane & 15)) * LS_RS + koff + ((lane >> 4) << 4);
                const unsigned b_off =
                    (warp_n * 32 + (lane & 7) + ((lane >> 4) << 3)) * LS_RS +
                    koff + (((lane >> 3) & 1) << 4);

                unsigned aH[4], aL[4], bH[4][2], bL[4][2];
                ldmatrix_x4(aH, sAh + a_off);
                ldmatrix_x4(aL, sAl + a_off);
#pragma unroll
                for (int np = 0; np < 2; np++) {
                    unsigned r4[4];
                    ldmatrix_x4(r4, sBh + b_off + np * 16 * LS_RS);
                    bH[np * 2][0] = r4[0]; bH[np * 2][1] = r4[1];
                    bH[np * 2 + 1][0] = r4[2]; bH[np * 2 + 1][1] = r4[3];
                    ldmatrix_x4(r4, sBl + b_off + np * 16 * LS_RS);
                    bL[np * 2][0] = r4[0]; bL[np * 2][1] = r4[1];
                    bL[np * 2 + 1][0] = r4[2]; bL[np * 2 + 1][1] = r4[3];
                }

#pragma unroll
                for (int nt = 0; nt < 4; nt++) {
                    mma_bf16(acc[nt], aH, bH[nt]);
                    mma_bf16(acc[nt], aH, bL[nt]);
                    mma_bf16(acc[nt], aL, bH[nt]);
                }
            }

            __syncthreads();
            if (c + 2 < 32) issue_chunk((c + 2) * 32, c & 1);
        }
    }

    __syncthreads();   // all MMA reads done; safe to alias stage smem as zs

    // fragments -> z tile
    {
        int r = warp_m * 16 + (lane >> 2);
#pragma unroll
        for (int nt = 0; nt < 4; nt++) {
            int col = warp_n * 32 + nt * 8 + 2 * (lane & 3);
            *reinterpret_cast<float2*>(&zs[r][col]) =
                make_float2(acc[nt][0], acc[nt][1]);
            *reinterpret_cast<float2*>(&zs[r + 8][col]) =
                make_float2(acc[nt][2], acc[nt][3]);
        }
    }
    __syncthreads();

    // fused gate update: 64 rows x 32 hidden units = 2048 items / 512 threads
    const float* embW = dir ? g_embWtb : g_embWtf;
    float* cptr = &g_c[dir][0];
    const int j0q = c0 >> 2;

#pragma unroll
    for (int it = 0; it < 4; it++) {
        int idx = it * 512 + tid;
        int r  = idx >> 5;     // 0..63
        int jj = idx & 31;     // 0..31
        int j = j0q + jj;

        float4 z4 = *reinterpret_cast<const float4*>(&zs[r][jj * 4]);
        int tok = toks[r];
        float4 ew = *reinterpret_cast<const float4*>(
            &embW[(size_t)tok * G4H + (j << 2)]);
        float zi = z4.x + ew.x;
        float zf = z4.y + ew.y;
        float zg = z4.z + ew.z;
        float zo = z4.w + ew.w;

        float ig = sigmoidf_fast(zi);
        float fg = sigmoidf_fast(zf);
        float og = sigmoidf_fast(zo);
        float gg = dir ? fmaxf(zg, 0.f) : tanhf(zg);

        int ci = (b0 + r) * Hq + j;
        float cv = fg * cptr[ci] + ig * gg;
        cptr[ci] = cv;
        float hc = dir ? fmaxf(cv, 0.f) : tanhf(cv);
        float hv = og * hc;

        size_t ao = ((size_t)(b0 + r) * Sq + s) * Kout + dir * Hq + j;
        __nv_bfloat16 hi = __float2bfloat16(hv);
        g_Ahi[ao] = hi;
        g_Alo[ao] = __float2bfloat16(hv - __bfloat162float(hi));
    }
}

// ---------------------------------------------------------------------------
// Output GEMM via HMMA split-bf16:
//   out[m][n] = Ahi*Bhi + Ahi*Blo + Alo*Bhi + bd[n]
// launch_bounds(256,2): regs capped at 128 so 2 CTAs co-reside (160KB smem).
// ---------------------------------------------------------------------------
#define OG_BK       32
#define OG_CHUNKS   (Kout / OG_BK)      // 64
#define OG_RSTRIDE  80
#define OG_TILE_B   (128 * OG_RSTRIDE)  // 10240
#define OG_STAGE_B  (4 * OG_TILE_B)
#define OG_SMEM     (2 * OG_STAGE_B)    // 81920

__global__ __launch_bounds__(256, 2) void out_gemm_kernel(
    const __nv_bfloat16* __restrict__ Ahi, const __nv_bfloat16* __restrict__ Alo,
    const __nv_bfloat16* __restrict__ Bhi, const __nv_bfloat16* __restrict__ Blo,
    const float* __restrict__ bd, float* __restrict__ out)
{
    extern __shared__ char smem[];
    const unsigned sb = smem_to_u32(smem);
    const int tid = threadIdx.x;
    const int wid = tid >> 5;
    const int lane = tid & 31;
    const int warp_m = wid >> 2;
    const int warp_n = wid & 3;
    const int n0 = blockIdx.x * 128;
    const int m0 = blockIdx.y * 128;

    const __nv_bfloat16* srcs[4] = {Ahi, Alo, Bhi, Blo};
    const int rowbase[4] = {m0, m0, n0, n0};

    auto issue_chunk = [&](int kc, int buf) {
        const unsigned bb = sb + buf * OG_STAGE_B;
#pragma unroll
        for (int i = 0; i < 8; i++) {
            int id   = i * 256 + tid;
            int tile = id >> 9;
            int rem  = id & 511;
            int r    = rem >> 2;
            int ch   = rem & 3;
            unsigned dst = bb + tile * OG_TILE_B + r * OG_RSTRIDE + ch * 16;
            const void* g = srcs[tile] +
                            (size_t)(rowbase[tile] + r) * Kout + kc + ch * 8;
            cp_async16(dst, g);
        }
        CP_COMMIT();
    };

    float acc[4][4][4];
#pragma unroll
    for (int mt = 0; mt < 4; mt++)
#pragma unroll
        for (int nt = 0; nt < 4; nt++)
#pragma unroll
            for (int q = 0; q < 4; q++) acc[mt][nt][q] = 0.f;

    issue_chunk(0, 0);
    issue_chunk(OG_BK, 1);

    for (int c = 0; c < OG_CHUNKS; c++) {
        if (c < OG_CHUNKS - 1) { CP_WAIT(1); } else { CP_WAIT(0); }
        __syncthreads();

        const unsigned bb  = sb + (c & 1) * OG_STAGE_B;
        const unsigned sAh = bb;
        const unsigned sAl = bb + OG_TILE_B;
        const unsigned sBh = bb + 2 * OG_TILE_B;
        const unsigned sBl = bb + 3 * OG_TILE_B;

#pragma unroll
        for (int kh = 0; kh < 2; kh++) {
            const int koff = kh * 32;
            const unsigned a_off =
                (warp_m * 64 + (lane & 15)) * OG_RSTRIDE + koff + ((lane >> 4) << 4);
            const unsigned b_off =
                (warp_n * 32 + (lane & 7) + ((lane >> 4) << 3)) * OG_RSTRIDE +
                koff + (((lane >> 3) & 1) << 4);

            unsigned aH[4][4], aL[4][4], bH[4][2], bL[4][2];
#pragma unroll
            for (int mt = 0; mt < 4; mt++) {
                ldmatrix_x4(aH[mt], sAh + a_off + mt * 16 * OG_RSTRIDE);
                ldmatrix_x4(aL[mt], sAl + a_off + mt * 16 * OG_RSTRIDE);
            }
#pragma unroll
            for (int np = 0; np < 2; np++) {
                unsigned r4[4];
                ldmatrix_x4(r4, sBh + b_off + np * 16 * OG_RSTRIDE);
                bH[np * 2][0] = r4[0]; bH[np * 2][1] = r4[1];
                bH[np * 2 + 1][0] = r4[2]; bH[np * 2 + 1][1] = r4[3];
                ldmatrix_x4(r4, sBl + b_off + np * 16 * OG_RSTRIDE);
                bL[np * 2][0] = r4[0]; bL[np * 2][1] = r4[1];
                bL[np * 2 + 1][0] = r4[2]; bL[np * 2 + 1][1] = r4[3];
            }

#pragma unroll
            for (int mt = 0; mt < 4; mt++)
#pragma unroll
                for (int nt = 0; nt < 4; nt++) {
                    mma_bf16(acc[mt][nt], aH[mt], bH[nt]);
                    mma_bf16(acc[mt][nt], aH[mt], bL[nt]);
                    mma_bf16(acc[mt][nt], aL[mt], bH[nt]);
                }
        }

        __syncthreads();
        if (c + 2 < OG_CHUNKS) issue_chunk((c + 2) * OG_BK, c & 1);
    }

#pragma unroll
    for (int mt = 0; mt < 4; mt++) {
        int r0 = m0 + warp_m * 64 + mt * 16 + (lane >> 2);
#pragma unroll
        for (int nt = 0; nt < 4; nt++) {
            int col = n0 + warp_n * 32 + nt * 8 + 2 * (lane & 3);
            float b0v = bd[col], b1v = bd[col + 1];
            float2 v0 = make_float2(acc[mt][nt][0] + b0v, acc[mt][nt][1] + b1v);
            float2 v1 = make_float2(acc[mt][nt][2] + b0v, acc[mt][nt][3] + b1v);
            *reinterpret_cast<float2*>(out + (size_t)r0 * Vq + col) = v0;
            *reinterpret_cast<float2*>(out + (size_t)(r0 + 8) * Vq + col) = v1;
        }
    }
}

// ---------------------------------------------------------------------------
// Launch
// ---------------------------------------------------------------------------
extern "C" void kernel_launch(void* const* d_in, const int* in_sizes, int n_in,
                              void* d_out, int out_size) {
    (void)in_sizes; (void)n_in; (void)out_size;
    const int*   tokens = (const int*)  d_in[0];
    const float* emb    = (const float*)d_in[1];
    const float* Wf     = (const float*)d_in[2];
    const float* Uf     = (const float*)d_in[3];
    const float* bf     = (const float*)d_in[4];
    const float* Wb     = (const float*)d_in[5];
    const float* Ub     = (const float*)d_in[6];
    const float* bb     = (const float*)d_in[7];
    const float* Wd     = (const float*)d_in[8];
    const float* bd     = (const float*)d_in[9];
    float* out = (float*)d_out;

    float *p_Wtf, *p_Wtb, *p_btf, *p_btb, *p_embWtf, *p_embWtb;
    __nv_bfloat16 *p_Ahi, *p_Alo, *p_Bhi, *p_Blo;
    cudaGetSymbolAddress((void**)&p_Wtf,    g_Wtf);
    cudaGetSymbolAddress((void**)&p_Wtb,    g_Wtb);
    cudaGetSymbolAddress((void**)&p_btf,    g_btf);
    cudaGetSymbolAddress((void**)&p_btb,    g_btb);
    cudaGetSymbolAddress((void**)&p_embWtf, g_embWtf);
    cudaGetSymbolAddress((void**)&p_embWtb, g_embWtb);
    cudaGetSymbolAddress((void**)&p_Ahi,    g_Ahi);
    cudaGetSymbolAddress((void**)&p_Alo,    g_Alo);
    cudaGetSymbolAddress((void**)&p_Bhi,    g_Bhi);
    cudaGetSymbolAddress((void**)&p_Blo,    g_Blo);

    cudaFuncSetAttribute(out_gemm_kernel,
                         cudaFuncAttributeMaxDynamicSharedMemorySize, OG_SMEM);
    cudaFuncSetAttribute(lstm_mma_step_kernel,
                         cudaFuncAttributeMaxDynamicSharedMemorySize, LS_SMEM);

    init_state_kernel<<<(Bq * Hq + 255) / 256, 256>>>();
    interleave_W_kernel<<<(Eq * G4H + 255) / 256, 256>>>(Wf, Wb, bf, bb);
    split_transpose_U_kernel<<<dim3(Hq / 32, Hq / 32, 8), dim3(32, 8)>>>(Uf, Ub);
    split_transpose_Wd_kernel<<<dim3(Vq / 32, Kout / 32), dim3(32, 8)>>>(Wd);

    // embWt = emb @ Wt + bt  (gate-interleaved, bias folded)
    gemm_bias_kernel<<<dim3(G4H / 128, Vq / 128), 256>>>(
        emb, p_Wtf, p_btf, p_embWtf, Vq, G4H, Eq);
    gemm_bias_kernel<<<dim3(G4H / 128, Vq / 128), 256>>>(
        emb, p_Wtb, p_btb, p_embWtb, Vq, G4H, Eq);

    // 256 sequential recurrent steps (both directions per launch), HMMA
    for (int t = 0; t < Sq; t++) {
        lstm_mma_step_kernel<<<dim3(G4H / 128, Bq / 64, 2), 512, LS_SMEM>>>(
            tokens, t);
    }

    out_gemm_kernel<<<dim3(Vq / 128, Mout / 128), 256, OG_SMEM>>>(
        p_Ahi, p_Alo, p_Bhi, p_Blo, bd, out);
}